// round 12
// baseline (speedup 1.0000x reference)
#include <cuda_runtime.h>
#include <cstdint>

#define NQ 16
#define NL 8
#define BATCH 512
#define DIM 65536
#define BCHUNK 128
#define NCHUNK (BATCH / BCHUNK)
#define TB 16
#define NBT (BCHUNK / TB)

typedef unsigned long long ull;

// 256 MB state, packed complex (lo=re, hi=im), layout [slot][batch]
__device__ ull g_state[(size_t)DIM * BATCH];
// measurement partials [coset 0..255][batch][wire]
__device__ float g_part[(size_t)256 * BATCH * NQ];
// precomputed gate constants: [pass 0..15][8 gates x {C,S,-S}]
__device__ ull g_gp[16 * 24];
// precomputed merged-RZ diag phases: [layer][slot] = (pack2(c,c), pack2(-s,s))
__device__ ulonglong2 g_ph[NL][DIM];

struct PassArgs {
    unsigned short xcA[16];     // XOR-combos of masks 0-3 (linear in index)
    unsigned short xcB[16];     // XOR-combos of masks 4-7
    unsigned int   ctab[8];     // per coset bit: repbit | flA<<16 | flB<<20
    unsigned short smA[16];     // sign-words of xcA (last pass)
    unsigned short smB[16];     // sign-words of xcB (last pass)
    unsigned short sfb[8];      // sign-words of coset bits (last pass)
    int pidx, b0;               // pidx = layer*2 + half
};
struct PrepArgs {
    unsigned short rl[NL][16];  // Lrow rows at layer l (phi terms)
    unsigned short rlm[NL][16]; // Lrow rows at layer l-1 (omega terms), 0 for l=0
};

// ---- packed f32x2 helpers (Blackwell) -------------------------------------
__device__ __forceinline__ ull ffma2(ull a, ull b, ull c) {
    ull d;
    asm("fma.rn.f32x2 %0, %1, %2, %3;" : "=l"(d) : "l"(a), "l"(b), "l"(c));
    return d;
}
__device__ __forceinline__ ull fmul2(ull a, ull b) {
    ull d;
    asm("mul.rn.f32x2 %0, %1, %2;" : "=l"(d) : "l"(a), "l"(b));
    return d;
}
__device__ __forceinline__ ull swap2(ull a) {
    ull d;
    asm("{\n\t.reg .b32 lo, hi;\n\tmov.b64 {lo, hi}, %1;\n\tmov.b64 %0, {hi, lo};\n\t}"
        : "=l"(d) : "l"(a));
    return d;
}
__device__ __forceinline__ ull pack2(float lo, float hi) {
    ull d;
    asm("mov.b64 %0, {%1, %2};" : "=l"(d) : "f"(lo), "f"(hi));
    return d;
}
__device__ __forceinline__ float2 unpk(ull a) {
    float2 f;
    asm("mov.b64 {%0, %1}, %2;" : "=f"(f.x), "=f"(f.y) : "l"(a));
    return f;
}

// real RY butterflies: r0 = c*a0 - s*a1, r1 = s*a0 + c*a1 (componentwise)
__device__ __forceinline__ void bfly4_ry(ull* v, const ull* Gp, int gofs) {
#pragma unroll
    for (int g = 0; g < 4; g++) {
        ull C = Gp[(gofs + g) * 3 + 0];
        ull Sp = Gp[(gofs + g) * 3 + 1];
        ull Sn = Gp[(gofs + g) * 3 + 2];
#pragma unroll
        for (int j = 0; j < 16; j++) {
            if (j & (1 << g)) continue;
            int j1 = j | (1 << g);
            ull a0 = v[j], a1 = v[j1];
            v[j]  = ffma2(C, a0, fmul2(Sn, a1));
            v[j1] = ffma2(Sp, a0, fmul2(C, a1));
        }
    }
}

// fold per-CTA coset word: rep (low 16) | flA (16..19) | flB (20..23)
__device__ __forceinline__ unsigned foldc(unsigned bx, const unsigned* ct) {
    unsigned a = 0;
#pragma unroll
    for (int k = 0; k < 8; k++)
        if ((bx >> k) & 1) a ^= ct[k];
    return a;
}

// ---------------------------------------------------------------------------
// prep kernels (once per launch): gate constants + diag phase table
// ---------------------------------------------------------------------------
__global__ __launch_bounds__(128) void qsim_prep_gates(const float* __restrict__ wts) {
    int t = threadIdx.x;                  // 0..127 = (pass, gate)
    int pidx = t >> 3, g = t & 7;
    int layer = pidx >> 1, gbase = (pidx & 1) * 8;
    float th = wts[((size_t)layer * NQ + gbase + g) * 3 + 1];
    float c, s;
    sincosf(0.5f * th, &s, &c);
    g_gp[pidx * 24 + g * 3 + 0] = pack2(c, c);
    g_gp[pidx * 24 + g * 3 + 1] = pack2(s, s);
    g_gp[pidx * 24 + g * 3 + 2] = pack2(-s, -s);
}

__global__ __launch_bounds__(256) void qsim_prep_phase(const float* __restrict__ wts,
                                                       const PrepArgs qa) {
    __shared__ float ph16[16], om16[16];
    int gid = blockIdx.x * 256 + threadIdx.x;   // 0..524287
    int l = gid >> 16;
    unsigned p = (unsigned)(gid & 0xFFFF);
    if (threadIdx.x < 16) {
        int l2 = l > 0 ? l - 1 : 0;
        ph16[threadIdx.x] = wts[((size_t)l * NQ + threadIdx.x) * 3 + 0];
        om16[threadIdx.x] = wts[((size_t)l2 * NQ + threadIdx.x) * 3 + 2];
    }
    __syncthreads();
    float phv = 0.0f;
#pragma unroll
    for (int k = 0; k < 16; k++)
        if (__popc((unsigned)qa.rl[l][k] & p) & 1) phv += ph16[k];
#pragma unroll
    for (int k = 0; k < 16; k++)
        if (__popc((unsigned)qa.rlm[l][k] & p) & 1) phv += om16[k];
    float sp, cp;
    sincosf(phv, &sp, &cp);
    g_ph[l][p] = make_ulonglong2(pack2(cp, cp), pack2(-sp, sp));
}

// ---------------------------------------------------------------------------
// passB: pure 8xRY half-layer (leanest, hottest path)
// ---------------------------------------------------------------------------
__global__ __launch_bounds__(256, 4) void qsim_passB(const PassArgs pa) {
    __shared__ __align__(16) ull S[4096];
    __shared__ ull Gp[24];
    int tid = threadIdx.x;
    int b = tid & 15, thi = tid >> 4;
    unsigned cw = foldc(blockIdx.x, pa.ctab);
    unsigned rep = cw & 0xFFFFu, flA = (cw >> 16) & 15u, flB = (cw >> 20) & 15u;
    size_t off = (size_t)(pa.b0 + blockIdx.y * TB + b);
    unsigned baseA = rep ^ (unsigned)pa.xcB[thi] ^ (unsigned)pa.xcA[flA];
    if (tid < 24) Gp[tid] = g_gp[pa.pidx * 24 + tid];
    ull v[16];
#pragma unroll
    for (int j = 0; j < 16; j++)
        v[j] = g_state[(size_t)(baseA ^ (unsigned)pa.xcA[j]) * BATCH + off];
    __syncthreads();
    bfly4_ry(v, Gp, 0);
#pragma unroll
    for (int j = 0; j < 16; j++) S[thi * 256 + j * 16 + b] = v[j];
    __syncthreads();
    {
        int c0 = ((thi ^ (int)flA) << 4) + b;
#pragma unroll
        for (int k = 0; k < 16; k++) v[k] = S[((k ^ (int)flB) << 8) + c0];
    }
    bfly4_ry(v, Gp, 4);
    unsigned baseB = rep ^ (unsigned)pa.xcA[thi] ^ (unsigned)pa.xcB[flB];
#pragma unroll
    for (int k = 0; k < 16; k++)
        g_state[(size_t)(baseB ^ (unsigned)pa.xcB[k]) * BATCH + off] = v[k];
}

// ---------------------------------------------------------------------------
// passA: merged RZ diagonal (from table) + 8xRY
// ---------------------------------------------------------------------------
__global__ __launch_bounds__(256, 4) void qsim_passA(const PassArgs pa) {
    __shared__ __align__(16) ull S[4096];
    __shared__ ull Gp[24];
    int tid = threadIdx.x;
    int b = tid & 15, thi = tid >> 4;
    int layer = pa.pidx >> 1;
    unsigned cw = foldc(blockIdx.x, pa.ctab);
    unsigned rep = cw & 0xFFFFu, flA = (cw >> 16) & 15u, flB = (cw >> 20) & 15u;
    size_t off = (size_t)(pa.b0 + blockIdx.y * TB + b);
    unsigned baseA = rep ^ (unsigned)pa.xcB[thi] ^ (unsigned)pa.xcA[flA];
    if (tid < 24) Gp[tid] = g_gp[pa.pidx * 24 + tid];
    ull v[16];
#pragma unroll
    for (int j = 0; j < 16; j++) {
        unsigned p = baseA ^ (unsigned)pa.xcA[j];
        ull vj = g_state[(size_t)p * BATCH + off];
        ulonglong2 ph = g_ph[layer][p];
        v[j] = ffma2(ph.x, vj, fmul2(ph.y, swap2(vj)));
    }
    __syncthreads();
    bfly4_ry(v, Gp, 0);
#pragma unroll
    for (int j = 0; j < 16; j++) S[thi * 256 + j * 16 + b] = v[j];
    __syncthreads();
    {
        int c0 = ((thi ^ (int)flA) << 4) + b;
#pragma unroll
        for (int k = 0; k < 16; k++) v[k] = S[((k ^ (int)flB) << 8) + c0];
    }
    bfly4_ry(v, Gp, 4);
    unsigned baseB = rep ^ (unsigned)pa.xcA[thi] ^ (unsigned)pa.xcB[flB];
#pragma unroll
    for (int k = 0; k < 16; k++)
        g_state[(size_t)(baseB ^ (unsigned)pa.xcB[k]) * BATCH + off] = v[k];
}

// ---------------------------------------------------------------------------
// first: product-state synthesis + diag(phi_0, from table) + 8xRY
// ---------------------------------------------------------------------------
__global__ __launch_bounds__(256, 4) void qsim_first(const float* __restrict__ x,
                                                     const PassArgs pa) {
    __shared__ __align__(16) ull S[4096];
    __shared__ ull Gp[24];
    __shared__ float2 cst[NQ * TB];
    int tid = threadIdx.x;
    int b = tid & 15, thi = tid >> 4;
    unsigned cw = foldc(blockIdx.x, pa.ctab);
    unsigned rep = cw & 0xFFFFu, flA = (cw >> 16) & 15u, flB = (cw >> 20) & 15u;
    size_t off = (size_t)(pa.b0 + blockIdx.y * TB + b);
    unsigned baseA = rep ^ (unsigned)pa.xcB[thi] ^ (unsigned)pa.xcA[flA];
    if (tid < 24) Gp[tid] = g_gp[pa.pidx * 24 + tid];
    {
        int wi = tid >> 4, bb2 = tid & 15;
        float s, c;
        sincospif(0.5f * x[(pa.b0 + blockIdx.y * TB + bb2) * NQ + wi], &s, &c);
        cst[wi * TB + bb2] = make_float2(c, s);
    }
    __syncthreads();
    ull v[16];
#pragma unroll
    for (int j = 0; j < 16; j++) {
        unsigned p = baseA ^ (unsigned)pa.xcA[j];
        float a = 1.0f;
#pragma unroll
        for (int i = 0; i < NQ; i++) {
            float2 c = cst[i * TB + b];
            a *= ((p >> i) & 1) ? c.y : c.x;
        }
        ulonglong2 ph = g_ph[0][p];
        ull vj = pack2(a, 0.0f);
        v[j] = ffma2(ph.x, vj, fmul2(ph.y, swap2(vj)));
    }
    bfly4_ry(v, Gp, 0);
#pragma unroll
    for (int j = 0; j < 16; j++) S[thi * 256 + j * 16 + b] = v[j];
    __syncthreads();
    {
        int c0 = ((thi ^ (int)flA) << 4) + b;
#pragma unroll
        for (int k = 0; k < 16; k++) v[k] = S[((k ^ (int)flB) << 8) + c0];
    }
    bfly4_ry(v, Gp, 4);
    unsigned baseB = rep ^ (unsigned)pa.xcA[thi] ^ (unsigned)pa.xcB[flB];
#pragma unroll
    for (int k = 0; k < 16; k++)
        g_state[(size_t)(baseB ^ (unsigned)pa.xcB[k]) * BATCH + off] = v[k];
}

// ---------------------------------------------------------------------------
// last: 8xRY + fused <Z_i> measurement (no state writeback)
// ---------------------------------------------------------------------------
__global__ __launch_bounds__(256, 4) void qsim_last(const PassArgs pa) {
    __shared__ __align__(16) ull S[4096];
    __shared__ ull Gp[24];
    int tid = threadIdx.x;
    int b = tid & 15, thi = tid >> 4;
    unsigned cw = foldc(blockIdx.x, pa.ctab);
    unsigned rep = cw & 0xFFFFu, flA = (cw >> 16) & 15u, flB = (cw >> 20) & 15u;
    int bbase = pa.b0 + blockIdx.y * TB;
    size_t off = (size_t)bbase + b;
    unsigned baseA = rep ^ (unsigned)pa.xcB[thi] ^ (unsigned)pa.xcA[flA];
    if (tid < 24) Gp[tid] = g_gp[pa.pidx * 24 + tid];
    ull v[16];
#pragma unroll
    for (int j = 0; j < 16; j++)
        v[j] = g_state[(size_t)(baseA ^ (unsigned)pa.xcA[j]) * BATCH + off];
    __syncthreads();
    bfly4_ry(v, Gp, 0);
#pragma unroll
    for (int j = 0; j < 16; j++) S[thi * 256 + j * 16 + b] = v[j];
    __syncthreads();
    {
        int c0 = ((thi ^ (int)flA) << 4) + b;
#pragma unroll
        for (int k = 0; k < 16; k++) v[k] = S[((k ^ (int)flB) << 8) + c0];
    }
    bfly4_ry(v, Gp, 4);
    // fused measurement: sign-words are GF(2)-linear in slot index
    unsigned swbase = 0;
#pragma unroll
    for (int k = 0; k < 8; k++)
        if ((blockIdx.x >> k) & 1) swbase ^= pa.sfb[k];
    swbase ^= (unsigned)pa.smA[thi] ^ (unsigned)pa.smB[flB];
    float acc[16];
#pragma unroll
    for (int i = 0; i < 16; i++) acc[i] = 0.0f;
#pragma unroll
    for (int k = 0; k < 16; k++) {
        float2 f = unpk(v[k]);
        float w = f.x * f.x + f.y * f.y;
        unsigned sw = swbase ^ (unsigned)pa.smB[k];
#pragma unroll
        for (int i = 0; i < 16; i++)
            acc[i] += ((sw >> i) & 1) ? -w : w;
    }
    __syncthreads();
    float* Sf = (float*)S;
#pragma unroll
    for (int i = 0; i < 16; i++) Sf[tid * 17 + i] = acc[i];
    __syncthreads();
    int bb = tid >> 4, ii = tid & 15;
    float s = 0.0f;
#pragma unroll
    for (int t = 0; t < 16; t++) s += Sf[(t * 16 + bb) * 17 + ii];
    g_part[(size_t)blockIdx.x * (BATCH * NQ) + (size_t)(bbase + bb) * NQ + ii] = s;
}

// Final deterministic reduction over 256 cosets -> out[b*16+i]
__global__ __launch_bounds__(256) void qsim_final(float* __restrict__ out) {
    int v = blockIdx.x * 256 + threadIdx.x;
    float s = 0.0f;
    for (int c = 0; c < 256; c++) s += g_part[(size_t)c * (BATCH * NQ) + v];
    out[v] = s;
}

// ---------------------------------------------------------------------------
static unsigned par16(unsigned v) {
    v ^= v >> 8; v ^= v >> 4; v ^= v >> 2; v ^= v >> 1;
    return v & 1u;
}

extern "C" void kernel_launch(void* const* d_in, const int* in_sizes, int n_in,
                              void* d_out, int out_size) {
    const float* x = (const float*)d_in[0];
    const float* w = (const float*)d_in[1];
    float* out = (float*)d_out;

    // Host-side GF(2) tracking of the CNOT network.
    unsigned short Lrow[NQ], Licol[NQ];
    unsigned short LrowHist[NL][NQ];
    unsigned char freeposH[NL][2][8];
    for (int i = 0; i < NQ; i++) { Lrow[i] = (unsigned short)(1u << i); Licol[i] = (unsigned short)(1u << i); }

    static PassArgs pa[NL][2];
    static PrepArgs qa;
    for (int l = 0; l < NL; l++) {
        for (int i = 0; i < NQ; i++) LrowHist[l][i] = Lrow[i];
        for (int half = 0; half < 2; half++) {
            PassArgs& a = pa[l][half];
            a.pidx = l * 2 + half; a.b0 = 0;
            unsigned short mask[8], selrow[8];
            for (int k = 0; k < 8; k++) {
                mask[k] = Licol[half * 8 + k];
                selrow[k] = Lrow[half * 8 + k];
            }
            for (int j = 0; j < 16; j++) {
                unsigned vA = 0, vB = 0;
                for (int bit = 0; bit < 4; bit++)
                    if ((j >> bit) & 1) { vA ^= mask[bit]; vB ^= mask[4 + bit]; }
                a.xcA[j] = (unsigned short)vA;
                a.xcB[j] = (unsigned short)vB;
            }
            for (int j = 0; j < 16; j++) { a.smA[j] = 0; a.smB[j] = 0; }
            for (int k = 0; k < 8; k++) a.sfb[k] = 0;
            // RREF over the 8 masks -> pivot bits; free bits index coset reps
            unsigned short red[8]; int piv[8]; unsigned pivmask = 0;
            for (int k = 0; k < 8; k++) {
                unsigned short vv = mask[k];
                for (int j = 0; j < k; j++)
                    if ((vv >> piv[j]) & 1) vv ^= red[j];
                int pbit = 0;
                while (!((vv >> pbit) & 1)) pbit++;
                piv[k] = pbit; red[k] = vv; pivmask |= (1u << pbit);
                for (int j = 0; j < k; j++)
                    if ((red[j] >> pbit) & 1) red[j] ^= vv;
            }
            int f = 0;
            unsigned char fp[8];
            for (int bit = 0; bit < NQ; bit++)
                if (!((pivmask >> bit) & 1)) fp[f++] = (unsigned char)bit;
            for (int k = 0; k < 8; k++) freeposH[l][half][k] = fp[k];
            // fused coset table: repbit | flA<<16 | flB<<20 per coset bit
            for (int k = 0; k < 8; k++) {
                unsigned fa = 0, fb = 0;
                for (int g = 0; g < 4; g++) {
                    fa |= (unsigned)((selrow[g] >> fp[k]) & 1) << g;
                    fb |= (unsigned)((selrow[4 + g] >> fp[k]) & 1) << g;
                }
                a.ctab[k] = (1u << fp[k]) | (fa << 16) | (fb << 20);
            }
        }
        int r = l % (NQ - 1) + 1;
        for (int i = 0; i < NQ; i++) {
            int c = i, t = (i + r) % NQ;
            Lrow[t] = (unsigned short)(Lrow[t] ^ Lrow[c]);
            Licol[c] = (unsigned short)(Licol[c] ^ Licol[t]);
        }
    }
    // prep args: rows selecting phi_l / omega_{l-1} terms per layer
    for (int l = 0; l < NL; l++)
        for (int k = 0; k < 16; k++) {
            qa.rl[l][k] = LrowHist[l][k];
            qa.rlm[l][k] = (l > 0) ? LrowHist[l - 1][k] : (unsigned short)0;
        }
    // sign-words for the fused measurement (final Lrow, last pass's combos)
    {
        PassArgs& lp = pa[NL - 1][1];
        for (int j = 0; j < 16; j++) {
            unsigned sa = 0, sb = 0;
            for (int i = 0; i < NQ; i++) {
                sa |= par16((unsigned)Lrow[i] & lp.xcA[j]) << i;
                sb |= par16((unsigned)Lrow[i] & lp.xcB[j]) << i;
            }
            lp.smA[j] = (unsigned short)sa;
            lp.smB[j] = (unsigned short)sb;
        }
        for (int k = 0; k < 8; k++) {
            unsigned sf = 0;
            for (int i = 0; i < NQ; i++)
                sf |= par16((unsigned)Lrow[i] & (1u << freeposH[NL - 1][1][k])) << i;
            lp.sfb[k] = (unsigned short)sf;
        }
    }

    qsim_prep_gates<<<1, 128>>>(w);
    qsim_prep_phase<<<(NL * DIM) / 256, 256>>>(w, qa);

    dim3 grid(256, NBT);
    for (int c = 0; c < NCHUNK; c++) {
        int b0 = c * BCHUNK;
        for (int l = 0; l < NL; l++)
            for (int half = 0; half < 2; half++) {
                PassArgs a = pa[l][half];
                a.b0 = b0;
                bool first = (l == 0 && half == 0);
                bool last = (l == NL - 1 && half == 1);
                if (first)            qsim_first<<<grid, 256>>>(x, a);
                else if (last)        qsim_last<<<grid, 256>>>(a);
                else if (half == 0)   qsim_passA<<<grid, 256>>>(a);
                else                  qsim_passB<<<grid, 256>>>(a);
            }
    }
    qsim_final<<<32, 256>>>(out);
}

// round 13
// speedup vs baseline: 1.0345x; 1.0345x over previous
#include <cuda_runtime.h>
#include <cstdint>

#define NQ 16
#define NL 8
#define BATCH 512
#define DIM 65536
#define BCHUNK 128
#define NCHUNK (BATCH / BCHUNK)
#define TB 16
#define NBT (BCHUNK / TB)

typedef unsigned long long ull;

// 256 MB state, packed complex (lo=re, hi=im), layout [slot][batch]
__device__ ull g_state[(size_t)DIM * BATCH];
// measurement partials [coset 0..255][batch][wire]
__device__ float g_part[(size_t)256 * BATCH * NQ];

struct PassArgs {
    unsigned short xcA[16];     // XOR-combos of masks 0-3 (linear in index)
    unsigned short xcB[16];     // XOR-combos of masks 4-7
    unsigned int   ctab[8];     // per coset bit: repbit | flA<<16 | flB<<20
    unsigned short smA[16];     // sign-words of xcA (last pass)
    unsigned short smB[16];     // sign-words of xcB (last pass)
    unsigned short sfb[8];      // sign-words of coset bits (last pass)
    unsigned int   WxcA[16];    // diag parity-words of xcA (pass A)
    unsigned int   WxcB[16];    // diag parity-words of xcB (pass A)
    unsigned int   Wfb[8];      // diag parity-words of coset bits (pass A)
    int layer, gbase, b0;
};

// ---- packed f32x2 helpers (Blackwell) -------------------------------------
__device__ __forceinline__ ull ffma2(ull a, ull b, ull c) {
    ull d;
    asm("fma.rn.f32x2 %0, %1, %2, %3;" : "=l"(d) : "l"(a), "l"(b), "l"(c));
    return d;
}
__device__ __forceinline__ ull fmul2(ull a, ull b) {
    ull d;
    asm("mul.rn.f32x2 %0, %1, %2;" : "=l"(d) : "l"(a), "l"(b));
    return d;
}
__device__ __forceinline__ ull swap2(ull a) {
    ull d;
    asm("{\n\t.reg .b32 lo, hi;\n\tmov.b64 {lo, hi}, %1;\n\tmov.b64 %0, {hi, lo};\n\t}"
        : "=l"(d) : "l"(a));
    return d;
}
__device__ __forceinline__ ull pack2(float lo, float hi) {
    ull d;
    asm("mov.b64 %0, {%1, %2};" : "=l"(d) : "f"(lo), "f"(hi));
    return d;
}
__device__ __forceinline__ float2 unpk(ull a) {
    float2 f;
    asm("mov.b64 {%0, %1}, %2;" : "=f"(f.x), "=f"(f.y) : "l"(a));
    return f;
}

// real RY butterflies: r0 = c*a0 - s*a1, r1 = s*a0 + c*a1 (componentwise)
__device__ __forceinline__ void bfly4_ry(ull* v, const ull* Gp, int gofs) {
#pragma unroll
    for (int g = 0; g < 4; g++) {
        ull C = Gp[(gofs + g) * 3 + 0];
        ull Sp = Gp[(gofs + g) * 3 + 1];
        ull Sn = Gp[(gofs + g) * 3 + 2];
#pragma unroll
        for (int j = 0; j < 16; j++) {
            if (j & (1 << g)) continue;
            int j1 = j | (1 << g);
            ull a0 = v[j], a1 = v[j1];
            v[j]  = ffma2(C, a0, fmul2(Sn, a1));
            v[j1] = ffma2(Sp, a0, fmul2(C, a1));
        }
    }
}

// fold per-CTA coset word: rep (low 16) | flA (16..19) | flB (20..23)
__device__ __forceinline__ unsigned foldc(unsigned bx, const unsigned* ct) {
    unsigned a = 0;
#pragma unroll
    for (int k = 0; k < 8; k++)
        if ((bx >> k) & 1) a ^= ct[k];
    return a;
}

__device__ __forceinline__ void gp_setup(ull* Gp, const float* wts, const PassArgs& pa, int tid) {
    if (tid < 8) {
        float th = wts[((size_t)pa.layer * NQ + pa.gbase + tid) * 3 + 1];
        float c, s;
        sincosf(0.5f * th, &s, &c);
        Gp[tid * 3 + 0] = pack2(c, c);
        Gp[tid * 3 + 1] = pack2(s, s);
        Gp[tid * 3 + 2] = pack2(-s, -s);
    }
}
// diag phase table entry for this thread's slot (32 GF(2)-selected terms)
__device__ __forceinline__ ulonglong2 diag_entry(const float* wts, const PassArgs& pa,
                                                 unsigned bx, int tid) {
    unsigned Wr = 0;
#pragma unroll
    for (int k = 0; k < 8; k++)
        if ((bx >> k) & 1) Wr ^= pa.Wfb[k];
    unsigned W = Wr ^ pa.WxcB[tid >> 4] ^ pa.WxcA[tid & 15];
    int l2 = pa.layer > 0 ? pa.layer - 1 : 0;
    float phv = 0.0f;
#pragma unroll
    for (int k = 0; k < 16; k++)
        phv += ((W >> k) & 1) ? __ldg(&wts[((size_t)pa.layer * NQ + k) * 3 + 0]) : 0.0f;
#pragma unroll
    for (int k = 0; k < 16; k++)
        phv += ((W >> (16 + k)) & 1) ? __ldg(&wts[((size_t)l2 * NQ + k) * 3 + 2]) : 0.0f;
    float sp, cp;
    sincosf(phv, &sp, &cp);
    return make_ulonglong2(pack2(cp, cp), pack2(-sp, sp));
}

// ---------------------------------------------------------------------------
// passB: pure 8xRY half-layer (leanest, hottest path)
// ---------------------------------------------------------------------------
__global__ __launch_bounds__(256, 4) void qsim_passB(const float* __restrict__ wts,
                                                     const PassArgs pa) {
    __shared__ __align__(16) ull S[4096];
    __shared__ ull Gp[24];
    int tid = threadIdx.x;
    int b = tid & 15, thi = tid >> 4;
    unsigned cw = foldc(blockIdx.x, pa.ctab);
    unsigned rep = cw & 0xFFFFu, flA = (cw >> 16) & 15u, flB = (cw >> 20) & 15u;
    ull* base = g_state + (size_t)(pa.b0 + blockIdx.y * TB + b);
    unsigned baseA = rep ^ (unsigned)pa.xcB[thi] ^ (unsigned)pa.xcA[flA];
    ull v[16];
#pragma unroll
    for (int j = 0; j < 16; j++)
        v[j] = __ldg(base + (((size_t)(baseA ^ (unsigned)pa.xcA[j])) << 9));
    gp_setup(Gp, wts, pa, tid);
    __syncthreads();
    bfly4_ry(v, Gp, 0);
#pragma unroll
    for (int j = 0; j < 16; j++) S[thi * 256 + j * 16 + b] = v[j];
    __syncthreads();
    {
        int c0 = ((thi ^ (int)flA) << 4) + b;
#pragma unroll
        for (int k = 0; k < 16; k++) v[k] = S[((k ^ (int)flB) << 8) + c0];
    }
    bfly4_ry(v, Gp, 4);
    unsigned baseB = rep ^ (unsigned)pa.xcA[thi] ^ (unsigned)pa.xcB[flB];
#pragma unroll
    for (int k = 0; k < 16; k++)
        base[((size_t)(baseB ^ (unsigned)pa.xcB[k])) << 9] = v[k];
}

// ---------------------------------------------------------------------------
// passA: merged RZ diagonal + 8xRY
// ---------------------------------------------------------------------------
__global__ __launch_bounds__(256, 4) void qsim_passA(const float* __restrict__ wts,
                                                     const PassArgs pa) {
    __shared__ __align__(16) ull S[4096];
    __shared__ ull Gp[24];
    __shared__ ulonglong2 Ph[256];
    int tid = threadIdx.x;
    int b = tid & 15, thi = tid >> 4;
    unsigned cw = foldc(blockIdx.x, pa.ctab);
    unsigned rep = cw & 0xFFFFu, flA = (cw >> 16) & 15u, flB = (cw >> 20) & 15u;
    ull* base = g_state + (size_t)(pa.b0 + blockIdx.y * TB + b);
    unsigned baseA = rep ^ (unsigned)pa.xcB[thi] ^ (unsigned)pa.xcA[flA];
    ull v[16];
#pragma unroll
    for (int j = 0; j < 16; j++)
        v[j] = __ldg(base + (((size_t)(baseA ^ (unsigned)pa.xcA[j])) << 9));
    gp_setup(Gp, wts, pa, tid);
    Ph[tid] = diag_entry(wts, pa, blockIdx.x, tid);
    __syncthreads();
#pragma unroll
    for (int j = 0; j < 16; j++) {
        ulonglong2 ph = Ph[thi * 16 + (j ^ (int)flA)];
        v[j] = ffma2(ph.x, v[j], fmul2(ph.y, swap2(v[j])));
    }
    bfly4_ry(v, Gp, 0);
#pragma unroll
    for (int j = 0; j < 16; j++) S[thi * 256 + j * 16 + b] = v[j];
    __syncthreads();
    {
        int c0 = ((thi ^ (int)flA) << 4) + b;
#pragma unroll
        for (int k = 0; k < 16; k++) v[k] = S[((k ^ (int)flB) << 8) + c0];
    }
    bfly4_ry(v, Gp, 4);
    unsigned baseB = rep ^ (unsigned)pa.xcA[thi] ^ (unsigned)pa.xcB[flB];
#pragma unroll
    for (int k = 0; k < 16; k++)
        base[((size_t)(baseB ^ (unsigned)pa.xcB[k])) << 9] = v[k];
}

// ---------------------------------------------------------------------------
// first: product-state synthesis + diag(phi_0) + 8xRY (layer 0 pass A)
// ---------------------------------------------------------------------------
__global__ __launch_bounds__(256, 4) void qsim_first(const float* __restrict__ x,
                                                     const float* __restrict__ wts,
                                                     const PassArgs pa) {
    __shared__ __align__(16) ull S[4096];
    __shared__ ull Gp[24];
    __shared__ ulonglong2 Ph[256];
    __shared__ float2 cst[NQ * TB];
    int tid = threadIdx.x;
    int b = tid & 15, thi = tid >> 4;
    unsigned cw = foldc(blockIdx.x, pa.ctab);
    unsigned rep = cw & 0xFFFFu, flA = (cw >> 16) & 15u, flB = (cw >> 20) & 15u;
    ull* base = g_state + (size_t)(pa.b0 + blockIdx.y * TB + b);
    unsigned baseA = rep ^ (unsigned)pa.xcB[thi] ^ (unsigned)pa.xcA[flA];
    gp_setup(Gp, wts, pa, tid);
    Ph[tid] = diag_entry(wts, pa, blockIdx.x, tid);
    {
        int wi = tid >> 4, bb2 = tid & 15;
        float s, c;
        sincospif(0.5f * x[(pa.b0 + blockIdx.y * TB + bb2) * NQ + wi], &s, &c);
        cst[wi * TB + bb2] = make_float2(c, s);
    }
    __syncthreads();
    ull v[16];
#pragma unroll
    for (int j = 0; j < 16; j++) {
        unsigned p = baseA ^ (unsigned)pa.xcA[j];
        float a = 1.0f;
#pragma unroll
        for (int i = 0; i < NQ; i++) {
            float2 c = cst[i * TB + b];
            a *= ((p >> i) & 1) ? c.y : c.x;
        }
        v[j] = pack2(a, 0.0f);
    }
#pragma unroll
    for (int j = 0; j < 16; j++) {
        ulonglong2 ph = Ph[thi * 16 + (j ^ (int)flA)];
        v[j] = ffma2(ph.x, v[j], fmul2(ph.y, swap2(v[j])));
    }
    bfly4_ry(v, Gp, 0);
#pragma unroll
    for (int j = 0; j < 16; j++) S[thi * 256 + j * 16 + b] = v[j];
    __syncthreads();
    {
        int c0 = ((thi ^ (int)flA) << 4) + b;
#pragma unroll
        for (int k = 0; k < 16; k++) v[k] = S[((k ^ (int)flB) << 8) + c0];
    }
    bfly4_ry(v, Gp, 4);
    unsigned baseB = rep ^ (unsigned)pa.xcA[thi] ^ (unsigned)pa.xcB[flB];
#pragma unroll
    for (int k = 0; k < 16; k++)
        base[((size_t)(baseB ^ (unsigned)pa.xcB[k])) << 9] = v[k];
}

// ---------------------------------------------------------------------------
// last: 8xRY + fused <Z_i> measurement (no state writeback)
// ---------------------------------------------------------------------------
__global__ __launch_bounds__(256, 4) void qsim_last(const float* __restrict__ wts,
                                                    const PassArgs pa) {
    __shared__ __align__(16) ull S[4096];
    __shared__ ull Gp[24];
    int tid = threadIdx.x;
    int b = tid & 15, thi = tid >> 4;
    unsigned cw = foldc(blockIdx.x, pa.ctab);
    unsigned rep = cw & 0xFFFFu, flA = (cw >> 16) & 15u, flB = (cw >> 20) & 15u;
    int bbase = pa.b0 + blockIdx.y * TB;
    ull* base = g_state + (size_t)(bbase + b);
    unsigned baseA = rep ^ (unsigned)pa.xcB[thi] ^ (unsigned)pa.xcA[flA];
    ull v[16];
#pragma unroll
    for (int j = 0; j < 16; j++)
        v[j] = __ldg(base + (((size_t)(baseA ^ (unsigned)pa.xcA[j])) << 9));
    gp_setup(Gp, wts, pa, tid);
    __syncthreads();
    bfly4_ry(v, Gp, 0);
#pragma unroll
    for (int j = 0; j < 16; j++) S[thi * 256 + j * 16 + b] = v[j];
    __syncthreads();
    {
        int c0 = ((thi ^ (int)flA) << 4) + b;
#pragma unroll
        for (int k = 0; k < 16; k++) v[k] = S[((k ^ (int)flB) << 8) + c0];
    }
    bfly4_ry(v, Gp, 4);
    // fused measurement: sign-words are GF(2)-linear in slot index
    unsigned swbase = 0;
#pragma unroll
    for (int k = 0; k < 8; k++)
        if ((blockIdx.x >> k) & 1) swbase ^= pa.sfb[k];
    swbase ^= (unsigned)pa.smA[thi] ^ (unsigned)pa.smB[flB];
    float acc[16];
#pragma unroll
    for (int i = 0; i < 16; i++) acc[i] = 0.0f;
#pragma unroll
    for (int k = 0; k < 16; k++) {
        float2 f = unpk(v[k]);
        float w = f.x * f.x + f.y * f.y;
        unsigned sw = swbase ^ (unsigned)pa.smB[k];
#pragma unroll
        for (int i = 0; i < 16; i++)
            acc[i] += ((sw >> i) & 1) ? -w : w;
    }
    __syncthreads();
    float* Sf = (float*)S;
#pragma unroll
    for (int i = 0; i < 16; i++) Sf[tid * 17 + i] = acc[i];
    __syncthreads();
    int bb = tid >> 4, ii = tid & 15;
    float s = 0.0f;
#pragma unroll
    for (int t = 0; t < 16; t++) s += Sf[(t * 16 + bb) * 17 + ii];
    g_part[(size_t)blockIdx.x * (BATCH * NQ) + (size_t)(bbase + bb) * NQ + ii] = s;
}

// Final deterministic reduction over 256 cosets -> out[b*16+i]
__global__ __launch_bounds__(256) void qsim_final(float* __restrict__ out) {
    int v = blockIdx.x * 256 + threadIdx.x;
    float s = 0.0f;
    for (int c = 0; c < 256; c++) s += g_part[(size_t)c * (BATCH * NQ) + v];
    out[v] = s;
}

// ---------------------------------------------------------------------------
static unsigned par16(unsigned v) {
    v ^= v >> 8; v ^= v >> 4; v ^= v >> 2; v ^= v >> 1;
    return v & 1u;
}

extern "C" void kernel_launch(void* const* d_in, const int* in_sizes, int n_in,
                              void* d_out, int out_size) {
    const float* x = (const float*)d_in[0];
    const float* w = (const float*)d_in[1];
    float* out = (float*)d_out;

    // Host-side GF(2) tracking of the CNOT network.
    unsigned short Lrow[NQ], Licol[NQ];
    unsigned short LrowHist[NL][NQ];
    unsigned char freeposH[NL][2][8];
    for (int i = 0; i < NQ; i++) { Lrow[i] = (unsigned short)(1u << i); Licol[i] = (unsigned short)(1u << i); }

    static PassArgs pa[NL][2];
    for (int l = 0; l < NL; l++) {
        for (int i = 0; i < NQ; i++) LrowHist[l][i] = Lrow[i];
        for (int half = 0; half < 2; half++) {
            PassArgs& a = pa[l][half];
            a.layer = l; a.gbase = half * 8; a.b0 = 0;
            unsigned short mask[8], selrow[8];
            for (int k = 0; k < 8; k++) {
                mask[k] = Licol[half * 8 + k];
                selrow[k] = Lrow[half * 8 + k];
            }
            for (int j = 0; j < 16; j++) {
                unsigned vA = 0, vB = 0;
                for (int bit = 0; bit < 4; bit++)
                    if ((j >> bit) & 1) { vA ^= mask[bit]; vB ^= mask[4 + bit]; }
                a.xcA[j] = (unsigned short)vA;
                a.xcB[j] = (unsigned short)vB;
            }
            for (int j = 0; j < 16; j++) { a.smA[j] = 0; a.smB[j] = 0; a.WxcA[j] = 0; a.WxcB[j] = 0; }
            for (int k = 0; k < 8; k++) { a.sfb[k] = 0; a.Wfb[k] = 0; }
            // RREF over the 8 masks -> pivot bits; free bits index coset reps
            unsigned short red[8]; int piv[8]; unsigned pivmask = 0;
            for (int k = 0; k < 8; k++) {
                unsigned short vv = mask[k];
                for (int j = 0; j < k; j++)
                    if ((vv >> piv[j]) & 1) vv ^= red[j];
                int pbit = 0;
                while (!((vv >> pbit) & 1)) pbit++;
                piv[k] = pbit; red[k] = vv; pivmask |= (1u << pbit);
                for (int j = 0; j < k; j++)
                    if ((red[j] >> pbit) & 1) red[j] ^= vv;
            }
            int f = 0;
            unsigned char fp[8];
            for (int bit = 0; bit < NQ; bit++)
                if (!((pivmask >> bit) & 1)) fp[f++] = (unsigned char)bit;
            for (int k = 0; k < 8; k++) freeposH[l][half][k] = fp[k];
            // fused coset table: repbit | flA<<16 | flB<<20 per coset bit
            for (int k = 0; k < 8; k++) {
                unsigned fa = 0, fb = 0;
                for (int g = 0; g < 4; g++) {
                    fa |= (unsigned)((selrow[g] >> fp[k]) & 1) << g;
                    fb |= (unsigned)((selrow[4 + g] >> fp[k]) & 1) << g;
                }
                a.ctab[k] = (1u << fp[k]) | (fa << 16) | (fb << 20);
            }
        }
        // diag parity-word tables for pass A of layer l
        {
            PassArgs& a = pa[l][0];
            unsigned rterm[32];
            for (int k = 0; k < 16; k++) rterm[k] = LrowHist[l][k];
            for (int k = 0; k < 16; k++) rterm[16 + k] = (l > 0) ? (unsigned)LrowHist[l - 1][k] : 0u;
            for (int j = 0; j < 16; j++) {
                unsigned wA = 0, wB = 0;
                for (int k = 0; k < 32; k++) {
                    wA |= par16(rterm[k] & a.xcA[j]) << k;
                    wB |= par16(rterm[k] & a.xcB[j]) << k;
                }
                a.WxcA[j] = wA; a.WxcB[j] = wB;
            }
            for (int kk = 0; kk < 8; kk++) {
                unsigned wf = 0;
                for (int k = 0; k < 32; k++)
                    wf |= par16(rterm[k] & (1u << freeposH[l][0][kk])) << k;
                a.Wfb[kk] = wf;
            }
        }
        int r = l % (NQ - 1) + 1;
        for (int i = 0; i < NQ; i++) {
            int c = i, t = (i + r) % NQ;
            Lrow[t] = (unsigned short)(Lrow[t] ^ Lrow[c]);
            Licol[c] = (unsigned short)(Licol[c] ^ Licol[t]);
        }
    }
    // sign-words for the fused measurement (final Lrow, last pass's combos)
    {
        PassArgs& lp = pa[NL - 1][1];
        for (int j = 0; j < 16; j++) {
            unsigned sa = 0, sb = 0;
            for (int i = 0; i < NQ; i++) {
                sa |= par16((unsigned)Lrow[i] & lp.xcA[j]) << i;
                sb |= par16((unsigned)Lrow[i] & lp.xcB[j]) << i;
            }
            lp.smA[j] = (unsigned short)sa;
            lp.smB[j] = (unsigned short)sb;
        }
        for (int k = 0; k < 8; k++) {
            unsigned sf = 0;
            for (int i = 0; i < NQ; i++)
                sf |= par16((unsigned)Lrow[i] & (1u << freeposH[NL - 1][1][k])) << i;
            lp.sfb[k] = (unsigned short)sf;
        }
    }

    dim3 grid(256, NBT);
    for (int c = 0; c < NCHUNK; c++) {
        int b0 = c * BCHUNK;
        for (int l = 0; l < NL; l++)
            for (int half = 0; half < 2; half++) {
                PassArgs a = pa[l][half];
                a.b0 = b0;
                bool first = (l == 0 && half == 0);
                bool last = (l == NL - 1 && half == 1);
                if (first)            qsim_first<<<grid, 256>>>(x, w, a);
                else if (last)        qsim_last<<<grid, 256>>>(w, a);
                else if (half == 0)   qsim_passA<<<grid, 256>>>(w, a);
                else                  qsim_passB<<<grid, 256>>>(w, a);
            }
    }
    qsim_final<<<32, 256>>>(out);
}